// round 7
// baseline (speedup 1.0000x reference)
#include <cuda_runtime.h>
#include <cstdint>

// ---------------- scratch (device globals; no allocs allowed) ----------------
__device__ float    g_hp[8192 * 64];        // h, tf32-rounded, f permuted: [(f%8)*8 + f/8]
__device__ float2   g_e1f1[8192];           // {exp(s1), exp(0.2*s1)}
__device__ float2   g_e2f2[8192];           // {exp(s2), exp(0.2*s2)}
__device__ uint32_t g_madj[64 * 8192 * 4];  // packed adj, q-major: [(q*8192+i)*4+c]
                                            // bit l of word c = adj[i][q*128 + l*4 + c]
__device__ float    g_part[8 * 8192 * 64];  // partial D per j-chunk (TRUE f order)
__device__ float    g_lpart[8 * 8192];      // partial softmax denom per j-chunk

// ---------------- helpers ----------------
__device__ __forceinline__ uint32_t smem_u32(const void* p) {
    uint32_t a;
    asm("{ .reg .u64 t; cvta.to.shared.u64 t, %1; cvt.u32.u64 %0, t; }" : "=r"(a) : "l"(p));
    return a;
}
__device__ __forceinline__ uint32_t tf32_rn(float x) {
    uint32_t u; asm("cvt.rna.tf32.f32 %0, %1;" : "=r"(u) : "f"(x));
    return u;
}
__device__ __forceinline__ void cp_async16(uint32_t saddr, const void* gaddr) {
    asm volatile("cp.async.cg.shared.global [%0], [%1], 16;" :: "r"(saddr), "l"(gaddr) : "memory");
}
#define CP_COMMIT() asm volatile("cp.async.commit_group;" ::: "memory")
#define CP_WAIT(n)  asm volatile("cp.async.wait_group %0;" :: "n"(n) : "memory")

__device__ __forceinline__ void mma_tf32(float* c, uint32_t a0, uint32_t a1, uint32_t a2,
                                         uint32_t a3, uint32_t b0, uint32_t b1) {
    asm volatile(
        "mma.sync.aligned.m16n8k8.row.col.f32.tf32.tf32.f32 "
        "{%0,%1,%2,%3}, {%4,%5,%6,%7}, {%8,%9}, {%0,%1,%2,%3};"
        : "+f"(c[0]), "+f"(c[1]), "+f"(c[2]), "+f"(c[3])
        : "r"(a0), "r"(a1), "r"(a2), "r"(a3), "r"(b0), "r"(b1));
}
__device__ __forceinline__ uint4 lds128(uint32_t addr) {
    uint4 v;
    asm volatile("ld.shared.v4.b32 {%0,%1,%2,%3}, [%4];"
                 : "=r"(v.x), "=r"(v.y), "=r"(v.z), "=r"(v.w) : "r"(addr));
    return v;
}
__device__ __forceinline__ float2 lds64f(uint32_t addr) {
    float2 v;
    asm volatile("ld.shared.v2.f32 {%0,%1}, [%2];" : "=f"(v.x), "=f"(v.y) : "r"(addr));
    return v;
}

// ============================================================================
// K1: h = input@W (W staged in smem) + adj bit-pack (overlaps prep's idle DRAM).
// grid 1024 x 256; block handles 8 rows of input AND packs 8 rows of adj
// (one row per warp, coalesced 512B reads, ballot -> q-major bitmask words).
// ============================================================================
static constexpr uint32_t PREP_SMEM = 64 * 1024 + 8 * 1024;

__global__ void __launch_bounds__(256)
gat_prep(const float* __restrict__ inp, const float* __restrict__ W,
         const float* __restrict__ a, const int* __restrict__ adj)
{
    extern __shared__ float dsm[];
    float* W_s  = dsm;          // 16384 floats
    float* in_s = dsm + 16384;  // 8*256 floats
    __shared__ float red[8][4];
    const int tid  = threadIdx.x;
    const int wp   = tid >> 5;
    const int lane = tid & 31;
    const int base = blockIdx.x * 8;

    // stage W + input rows
#pragma unroll
    for (int v = 0; v < 16; v++)
        reinterpret_cast<float4*>(W_s)[tid + v * 256] =
            reinterpret_cast<const float4*>(W)[tid + v * 256];
#pragma unroll
    for (int v = 0; v < 2; v++) {
        const int idx = tid + v * 256;
        reinterpret_cast<float4*>(in_s)[idx] =
            reinterpret_cast<const float4*>(inp)[(size_t)base * 64 + idx];
    }

    // ---- pack adj row (base+wp) into bitmasks, q-major layout
    {
        const int row = base + wp;
        const int4* asrc = reinterpret_cast<const int4*>(adj) + (size_t)row * 2048;
#pragma unroll 4
        for (int q = 0; q < 64; q++) {
            const int4 m = asrc[q * 32 + lane];
            const uint32_t b0 = __ballot_sync(0xFFFFFFFFu, m.x != 0);
            const uint32_t b1 = __ballot_sync(0xFFFFFFFFu, m.y != 0);
            const uint32_t b2 = __ballot_sync(0xFFFFFFFFu, m.z != 0);
            const uint32_t b3 = __ballot_sync(0xFFFFFFFFu, m.w != 0);
            if (lane == 0)
                *reinterpret_cast<uint4*>(&g_madj[((size_t)q * 8192 + row) * 4]) =
                    make_uint4(b0, b1, b2, b3);
        }
    }
    __syncthreads();

    const int f  = tid & 63;
    const int rg = tid >> 6;
    const float* inr0 = in_s + rg * 256;
    const float* inr1 = in_s + (rg + 4) * 256;
    float acc0 = 0.f, acc1 = 0.f;
#pragma unroll 16
    for (int k = 0; k < 256; k++) {
        const float w = W_s[k * 64 + f];
        acc0 += inr0[k] * w;
        acc1 += inr1[k] * w;
    }
    const int fp = (f & 7) * 8 + (f >> 3);  // permuted feature index
    g_hp[(size_t)(base + rg)     * 64 + fp] = __uint_as_float(tf32_rn(acc0));
    g_hp[(size_t)(base + rg + 4) * 64 + fp] = __uint_as_float(tf32_rn(acc1));

    const float a1 = __ldg(&a[f]);
    const float a2 = __ldg(&a[64 + f]);
    float s10 = acc0 * a1, s20 = acc0 * a2, s11 = acc1 * a1, s21 = acc1 * a2;
#pragma unroll
    for (int o = 16; o > 0; o >>= 1) {
        s10 += __shfl_xor_sync(0xFFFFFFFFu, s10, o);
        s20 += __shfl_xor_sync(0xFFFFFFFFu, s20, o);
        s11 += __shfl_xor_sync(0xFFFFFFFFu, s11, o);
        s21 += __shfl_xor_sync(0xFFFFFFFFu, s21, o);
    }
    if (lane == 0) { red[wp][0] = s10; red[wp][1] = s20; red[wp][2] = s11; red[wp][3] = s21; }
    __syncthreads();
    if (tid < 8) {
        const int rr = tid & 3;
        const int hi = tid >> 2;
        const float v1 = red[2 * rr][hi * 2 + 0] + red[2 * rr + 1][hi * 2 + 0];
        const float v2 = red[2 * rr][hi * 2 + 1] + red[2 * rr + 1][hi * 2 + 1];
        const int row = base + rr + hi * 4;
        g_e1f1[row] = make_float2(expf(v1), expf(0.2f * v1));
        g_e2f2[row] = make_float2(expf(v2), expf(0.2f * v2));
    }
}

// ============================================================================
// K2: masked attention + (P @ h) via mma.sync tf32.
// grid 256 = 32 i-tiles (256 rows) x 8 j-chunks (1024 cols); 256 thr, 2 CTA/SM.
// warp = 32 rows (two m16 A-fragments sharing each B-fragment).
// Masks: 4 L2-resident LDG.32 per warp-tile (contiguous 512B/warp, q-major),
// register-prefetched one tile ahead. l via ones-column MMA.
// ============================================================================
static constexpr int  HSTRIDE   = 68;                       // floats per smem h row
static constexpr uint32_t SM_E2F2 = 0;                      // 1024 float2 = 8192 B
static constexpr uint32_t SM_H0   = 8192;                   // 128*68*4 = 34816 B
static constexpr uint32_t SM_H1   = SM_H0 + 128 * HSTRIDE * 4;
static constexpr uint32_t SMEM_TOTAL = SM_H1 + 128 * HSTRIDE * 4;  // 77824 B
static constexpr uint32_t ONE_TF32 = 0x3f800000u;           // 1.0f (exact tf32)

__global__ void __launch_bounds__(256, 2)
gat_attn()
{
    extern __shared__ char smem[];
    const uint32_t sb = smem_u32(smem);
    const int tid = threadIdx.x;
    const int w   = tid >> 5;
    const int lane = tid & 31;
    const int g   = lane >> 2;  // fragment row within block
    const int ctg = lane & 3;   // k col
    const int it  = blockIdx.x >> 3;
    const int jq  = blockIdx.x & 7;
    const int ibase = it * 256;
    const int jbase = jq * 1024;
    const int rbase = ibase + w * 32;      // this warp's 32 rows

    // ---- preload E2F2 slice (1024 entries = 512 float4)
    {
        const float4* src = reinterpret_cast<const float4*>(&g_e2f2[jbase]);
        float4* dst = reinterpret_cast<float4*>(smem + SM_E2F2);
        dst[tid]       = src[tid];
        dst[tid + 256] = src[tid + 256];
    }

    // ---- preload h tile 0 via cp.async (8 x 16B per thread)
    {
        const float* src = &g_hp[(size_t)jbase * 64];
#pragma unroll
        for (int v = 0; v < 8; v++) {
            const int id = tid + v * 256;          // 0..2047 float4s
            const int r  = id >> 4, c4 = id & 15;
            cp_async16(sb + SM_H0 + (r * HSTRIDE + c4 * 4) * 4, src + r * 64 + c4 * 4);
        }
        CP_COMMIT();
    }

    const float2 ef0 = g_e1f1[rbase + g];
    const float2 ef1 = g_e1f1[rbase + g + 8];
    const float2 ef2 = g_e1f1[rbase + g + 16];
    const float2 ef3 = g_e1f1[rbase + g + 24];

    // mask pointer: word(t, ro) = mp[t*32768 + ro*4]   (q-major layout)
    const uint32_t* __restrict__ mp =
        g_madj + ((size_t)(jq * 8) * 8192 + rbase + g) * 4 + ctg;
    uint32_t wm0 = mp[0];
    uint32_t wm1 = mp[32];
    uint32_t wm2 = mp[64];
    uint32_t wm3 = mp[96];

    float C0[8][4], C1[8][4], S0[4], S1[4];
#pragma unroll
    for (int n = 0; n < 8; n++)
#pragma unroll
        for (int q = 0; q < 4; q++) { C0[n][q] = 0.f; C1[n][q] = 0.f; }
#pragma unroll
    for (int q = 0; q < 4; q++) { S0[q] = 0.f; S1[q] = 0.f; }

    for (int t = 0; t < 8; t++) {
        const uint32_t hb = (t & 1) ? SM_H1 : SM_H0;

        if (t < 7) {  // prefetch next h tile into other buffer
            const uint32_t hn = (t & 1) ? SM_H0 : SM_H1;
            const float* src = &g_hp[((size_t)jbase + (t + 1) * 128) * 64];
#pragma unroll
            for (int v = 0; v < 8; v++) {
                const int id = tid + v * 256;
                const int r  = id >> 4, c4 = id & 15;
                cp_async16(sb + hn + (r * HSTRIDE + c4 * 4) * 4, src + r * 64 + c4 * 4);
            }
            CP_COMMIT();
            CP_WAIT(1);
        } else {
            CP_WAIT(0);
        }
        __syncthreads();

        uint32_t r0 = wm0, r1 = wm1, r2 = wm2, r3 = wm3;
        if (t < 7) {  // prefetch next tile's mask words (L2-resident)
            const uint32_t* mp2 = mp + (size_t)(t + 1) * 32768;
            wm0 = mp2[0];
            wm1 = mp2[32];
            wm2 = mp2[64];
            wm3 = mp2[96];
        }

#pragma unroll 2
        for (int kk = 0; kk < 16; kk++) {
            const int lj = kk * 8;               // local j within tile
            const int jj = t * 128 + lj;         // j within chunk

            // column factors (broadcast LDS)
            const float2 c0 = lds64f(sb + SM_E2F2 + (jj + ctg) * 8);
            const float2 c1 = lds64f(sb + SM_E2F2 + (jj + ctg + 4) * 8);

            // P = adj ? max(E1*E2, F1*F2) : 0   (== exp(leaky(s1+s2)) masked)
            const float pL0 = (r0 & 1u) ? fmaxf(ef0.x * c0.x, ef0.y * c0.y) : 0.f;
            const float pH0 = (r0 & 2u) ? fmaxf(ef0.x * c1.x, ef0.y * c1.y) : 0.f;
            const float pL1 = (r1 & 1u) ? fmaxf(ef1.x * c0.x, ef1.y * c0.y) : 0.f;
            const float pH1 = (r1 & 2u) ? fmaxf(ef1.x * c1.x, ef1.y * c1.y) : 0.f;
            const float pL2 = (r2 & 1u) ? fmaxf(ef2.x * c0.x, ef2.y * c0.y) : 0.f;
            const float pH2 = (r2 & 2u) ? fmaxf(ef2.x * c1.x, ef2.y * c1.y) : 0.f;
            const float pL3 = (r3 & 1u) ? fmaxf(ef3.x * c0.x, ef3.y * c0.y) : 0.f;
            const float pH3 = (r3 & 2u) ? fmaxf(ef3.x * c1.x, ef3.y * c1.y) : 0.f;
            r0 >>= 2; r1 >>= 2; r2 >>= 2; r3 >>= 2;

            // A fragments (HW truncation bias cancels in D/l ratio)
            const uint32_t a00 = __float_as_uint(pL0), a01 = __float_as_uint(pL1);
            const uint32_t a02 = __float_as_uint(pH0), a03 = __float_as_uint(pH1);
            const uint32_t a10 = __float_as_uint(pL2), a11 = __float_as_uint(pL3);
            const uint32_t a12 = __float_as_uint(pH2), a13 = __float_as_uint(pH3);

            // B fragments: rows lj+ctg and lj+ctg+4, packed cols g*8 .. g*8+7
            const uint32_t rb0 = sb + hb + ((lj + ctg) * HSTRIDE + g * 8) * 4;
            const uint32_t rb1 = sb + hb + ((lj + ctg + 4) * HSTRIDE + g * 8) * 4;
            const uint4 bl0 = lds128(rb0);
            const uint4 bl1 = lds128(rb0 + 16);
            const uint4 bh0 = lds128(rb1);
            const uint4 bh1 = lds128(rb1 + 16);

            mma_tf32(C0[0], a00, a01, a02, a03, bl0.x, bh0.x);
            mma_tf32(C1[0], a10, a11, a12, a13, bl0.x, bh0.x);
            mma_tf32(C0[1], a00, a01, a02, a03, bl0.y, bh0.y);
            mma_tf32(C1[1], a10, a11, a12, a13, bl0.y, bh0.y);
            mma_tf32(C0[2], a00, a01, a02, a03, bl0.z, bh0.z);
            mma_tf32(C1[2], a10, a11, a12, a13, bl0.z, bh0.z);
            mma_tf32(C0[3], a00, a01, a02, a03, bl0.w, bh0.w);
            mma_tf32(C1[3], a10, a11, a12, a13, bl0.w, bh0.w);
            mma_tf32(C0[4], a00, a01, a02, a03, bl1.x, bh1.x);
            mma_tf32(C1[4], a10, a11, a12, a13, bl1.x, bh1.x);
            mma_tf32(C0[5], a00, a01, a02, a03, bl1.y, bh1.y);
            mma_tf32(C1[5], a10, a11, a12, a13, bl1.y, bh1.y);
            mma_tf32(C0[6], a00, a01, a02, a03, bl1.z, bh1.z);
            mma_tf32(C1[6], a10, a11, a12, a13, bl1.z, bh1.z);
            mma_tf32(C0[7], a00, a01, a02, a03, bl1.w, bh1.w);
            mma_tf32(C1[7], a10, a11, a12, a13, bl1.w, bh1.w);
            // row sums (l) via ones-column MMA
            mma_tf32(S0, a00, a01, a02, a03, ONE_TF32, ONE_TF32);
            mma_tf32(S1, a10, a11, a12, a13, ONE_TF32, ONE_TF32);
        }
        __syncthreads();
    }

    // ---- l write (S values identical across the 4 threads of each group)
    if (ctg == 0) {
        float* lp = &g_lpart[(size_t)jq * 8192];
        lp[rbase + g]      = S0[0];
        lp[rbase + g + 8]  = S0[2];
        lp[rbase + g + 16] = S1[0];
        lp[rbase + g + 24] = S1[2];
    }

    // ---- write D partials (TRUE f order): mma #nt covers f = nt*8 + mma-n
    float* d0 = &g_part[((size_t)jq * 8192 + rbase + g) * 64];
    float* d1 = d0 + 8 * 64;
    float* d2 = d0 + 16 * 64;
    float* d3 = d0 + 24 * 64;
#pragma unroll
    for (int nt = 0; nt < 8; nt++) {
        const int col = nt * 8 + 2 * ctg;
        *reinterpret_cast<float2*>(&d0[col]) = make_float2(C0[nt][0], C0[nt][1]);
        *reinterpret_cast<float2*>(&d1[col]) = make_float2(C0[nt][2], C0[nt][3]);
        *reinterpret_cast<float2*>(&d2[col]) = make_float2(C1[nt][0], C1[nt][1]);
        *reinterpret_cast<float2*>(&d3[col]) = make_float2(C1[nt][2], C1[nt][3]);
    }
}

// ============================================================================
// K3: combine 8 partials, normalize, elu. g_part is in TRUE f order.
// ============================================================================
__device__ __forceinline__ float eluf(float x) { return x > 0.f ? x : expm1f(x); }

__global__ void __launch_bounds__(256)
gat_final(float* __restrict__ out)
{
    const int gi = blockIdx.x * 256 + threadIdx.x;  // 0..131071
    const int i  = gi >> 4;
    const int c0 = (gi & 15) * 4;
    float4 acc = *reinterpret_cast<const float4*>(&g_part[(size_t)i * 64 + c0]);
    float l = g_lpart[i];
#pragma unroll
    for (int q = 1; q < 8; q++) {
        const float4 d = *reinterpret_cast<const float4*>(
            &g_part[((size_t)q * 8192 + i) * 64 + c0]);
        acc.x += d.x; acc.y += d.y; acc.z += d.z; acc.w += d.w;
        l += g_lpart[(size_t)q * 8192 + i];
    }
    const float inv = 1.0f / l;
    float4 o;
    o.x = eluf(acc.x * inv);
    o.y = eluf(acc.y * inv);
    o.z = eluf(acc.z * inv);
    o.w = eluf(acc.w * inv);
    *reinterpret_cast<float4*>(&out[(size_t)i * 64 + c0]) = o;
}

// ============================================================================
extern "C" void kernel_launch(void* const* d_in, const int* in_sizes, int n_in,
                              void* d_out, int out_size)
{
    const float* inp = (const float*)d_in[0];
    const int*   adj = (const int*)d_in[1];
    const float* W   = (const float*)d_in[2];
    const float* a   = (const float*)d_in[3];
    float* out = (float*)d_out;

    cudaFuncSetAttribute((const void*)gat_prep,
                         cudaFuncAttributeMaxDynamicSharedMemorySize, PREP_SMEM);
    cudaFuncSetAttribute((const void*)gat_attn,
                         cudaFuncAttributeMaxDynamicSharedMemorySize, SMEM_TOTAL);

    gat_prep<<<1024, 256, PREP_SMEM>>>(inp, W, a, adj);
    gat_attn<<<256, 256, SMEM_TOTAL>>>();
    gat_final<<<512, 256>>>(out);
}

// round 8
// speedup vs baseline: 1.2621x; 1.2621x over previous
#include <cuda_runtime.h>
#include <cstdint>

// ---------------- scratch (device globals; no allocs allowed) ----------------
__device__ uint32_t g_w16[4096 * 64];       // h fp16x2: [jp*64+fp] = (hi=h[2jp+1][f], lo=h[2jp][f]), fp=(f&7)*8+(f>>3)
__device__ float2   g_e1f1[8192];           // {exp(s1), exp(0.2*s1)}
__device__ float2   g_e2f2[8192];           // {exp(s2), exp(0.2*s2)}
__device__ float    g_part[8 * 8192 * 64];  // partial D per j-chunk (TRUE f order)
__device__ float    g_lpart[8 * 8192];      // partial softmax denom per j-chunk

// ---------------- helpers ----------------
__device__ __forceinline__ uint32_t smem_u32(const void* p) {
    uint32_t a;
    asm("{ .reg .u64 t; cvta.to.shared.u64 t, %1; cvt.u32.u64 %0, t; }" : "=r"(a) : "l"(p));
    return a;
}
__device__ __forceinline__ void cp_async16(uint32_t saddr, const void* gaddr) {
    asm volatile("cp.async.cg.shared.global [%0], [%1], 16;" :: "r"(saddr), "l"(gaddr) : "memory");
}
#define CP_COMMIT() asm volatile("cp.async.commit_group;" ::: "memory")
#define CP_WAIT(n)  asm volatile("cp.async.wait_group %0;" :: "n"(n) : "memory")

__device__ __forceinline__ void mma_f16(float* c, uint32_t a0, uint32_t a1, uint32_t a2,
                                        uint32_t a3, uint32_t b0, uint32_t b1) {
    asm volatile(
        "mma.sync.aligned.m16n8k16.row.col.f32.f16.f16.f32 "
        "{%0,%1,%2,%3}, {%4,%5,%6,%7}, {%8,%9}, {%0,%1,%2,%3};"
        : "+f"(c[0]), "+f"(c[1]), "+f"(c[2]), "+f"(c[3])
        : "r"(a0), "r"(a1), "r"(a2), "r"(a3), "r"(b0), "r"(b1));
}
__device__ __forceinline__ uint4 lds128(uint32_t addr) {
    uint4 v;
    asm volatile("ld.shared.v4.b32 {%0,%1,%2,%3}, [%4];"
                 : "=r"(v.x), "=r"(v.y), "=r"(v.z), "=r"(v.w) : "r"(addr));
    return v;
}
__device__ __forceinline__ float4 lds128f(uint32_t addr) {
    float4 v;
    asm volatile("ld.shared.v4.f32 {%0,%1,%2,%3}, [%4];"
                 : "=f"(v.x), "=f"(v.y), "=f"(v.z), "=f"(v.w) : "r"(addr));
    return v;
}
__device__ __forceinline__ uint2 lds64u(uint32_t addr) {
    uint2 v;
    asm volatile("ld.shared.v2.b32 {%0,%1}, [%2];" : "=r"(v.x), "=r"(v.y) : "r"(addr));
    return v;
}
// select v if bit `31-sh_from_31...`: t = m<<sh puts target bit at sign; slct picks v when t<0
__device__ __forceinline__ float msel(uint32_t m, int sh, float v) {
    float r;
    asm("{ .reg .b32 t; shl.b32 t, %1, %2; slct.f32.s32 %0, 0f00000000, %3, t; }"
        : "=f"(r) : "r"(m), "r"(sh), "f"(v));
    return r;
}
__device__ __forceinline__ uint32_t pack16(float hi, float lo) {
    uint32_t d;
    asm("cvt.rn.f16x2.f32 %0, %1, %2;" : "=r"(d) : "f"(hi), "f"(lo));
    return d;
}

// ============================================================================
// K1: h = input@W (W staged in smem); writes fp16x2 j-pair-packed h and
// E1F1/E2F2 factors. grid 512 x 512 threads; block handles 16 rows.
// ============================================================================
static constexpr uint32_t PREP_SMEM = 64 * 1024 + 16 * 1024;

__global__ void __launch_bounds__(512)
gat_prep(const float* __restrict__ inp, const float* __restrict__ W,
         const float* __restrict__ a)
{
    extern __shared__ float dsm[];
    float* W_s  = dsm;          // 16384 floats
    float* in_s = dsm + 16384;  // 16*256 floats
    __shared__ float red[16][4];
    const int tid  = threadIdx.x;
    const int base = blockIdx.x * 16;

#pragma unroll
    for (int v = 0; v < 8; v++)
        reinterpret_cast<float4*>(W_s)[tid + v * 512] =
            reinterpret_cast<const float4*>(W)[tid + v * 512];
#pragma unroll
    for (int v = 0; v < 2; v++)
        reinterpret_cast<float4*>(in_s)[tid + v * 512] =
            reinterpret_cast<const float4*>(inp)[(size_t)base * 64 + tid + v * 512];
    __syncthreads();

    const int f  = tid & 63;
    const int rg = tid >> 6;                 // 0..7 -> rows base+2rg, base+2rg+1
    const float* inr0 = in_s + 2 * rg * 256;
    const float* inr1 = inr0 + 256;
    float acc0 = 0.f, acc1 = 0.f;
#pragma unroll 16
    for (int k = 0; k < 256; k++) {
        const float w = W_s[k * 64 + f];
        acc0 += inr0[k] * w;
        acc1 += inr1[k] * w;
    }
    const int fp = (f & 7) * 8 + (f >> 3);   // permuted feature index
    g_w16[(size_t)(blockIdx.x * 8 + rg) * 64 + fp] = pack16(acc1, acc0);

    const float a1 = __ldg(&a[f]);
    const float a2 = __ldg(&a[64 + f]);
    float s10 = acc0 * a1, s20 = acc0 * a2, s11 = acc1 * a1, s21 = acc1 * a2;
#pragma unroll
    for (int o = 16; o > 0; o >>= 1) {
        s10 += __shfl_xor_sync(0xFFFFFFFFu, s10, o);
        s20 += __shfl_xor_sync(0xFFFFFFFFu, s20, o);
        s11 += __shfl_xor_sync(0xFFFFFFFFu, s11, o);
        s21 += __shfl_xor_sync(0xFFFFFFFFu, s21, o);
    }
    const int w = tid >> 5;  // warps 2rg, 2rg+1 hold f-halves
    if ((tid & 31) == 0) { red[w][0] = s10; red[w][1] = s20; red[w][2] = s11; red[w][3] = s21; }
    __syncthreads();
    if (tid < 16) {
        const int rr = tid & 7;
        const int hi = tid >> 3;             // 0: acc0 row, 1: acc1 row
        const float v1 = red[2 * rr][hi * 2 + 0] + red[2 * rr + 1][hi * 2 + 0];
        const float v2 = red[2 * rr][hi * 2 + 1] + red[2 * rr + 1][hi * 2 + 1];
        const int row = base + 2 * rr + hi;
        g_e1f1[row] = make_float2(expf(v1), expf(0.2f * v1));
        g_e2f2[row] = make_float2(expf(v2), expf(0.2f * v2));
    }
}

// ============================================================================
// K2: fused adj-pack + masked attention + (P @ h) via mma.sync fp16 k16.
// grid 256 = 32 i-tiles (256 rows) x 8 j-chunks (1024 cols); 256 thr, 2/SM.
// warp = 32 rows. adj packed in-kernel, software-pipelined inside kstep loop.
// l via ones-column MMA.
// ============================================================================
static constexpr uint32_t HROW    = 272;                 // bytes per jp-row (64 words + pad)
static constexpr uint32_t SM_E2F2 = 0;                   // 8192 B
static constexpr uint32_t SM_MASK = 8192;                // 2 x 4096 B
static constexpr uint32_t SM_H0   = 16384;               // 64*272 = 17408 B
static constexpr uint32_t SM_H1   = SM_H0 + 64 * HROW;
static constexpr uint32_t SMEM_TOTAL = SM_H1 + 64 * HROW;  // 51200 B
static constexpr uint32_t ONE2 = 0x3C003C00u;            // (1.0h, 1.0h)

__global__ void __launch_bounds__(256, 2)
gat_attn(const int* __restrict__ adj)
{
    extern __shared__ char smem[];
    const uint32_t sb = smem_u32(smem);
    const int tid  = threadIdx.x;
    const int w    = tid >> 5;
    const int lane = tid & 31;
    const int g    = lane >> 2;
    const int ctg  = lane & 3;
    const int it   = blockIdx.x >> 3;
    const int jq   = blockIdx.x & 7;
    const int ibase = it * 256;
    const int jbase = jq * 1024;
    const int rbase = ibase + w * 32;

    // ---- preload E2F2 slice (1024 float2 = 512 float4)
    {
        const float4* src = reinterpret_cast<const float4*>(&g_e2f2[jbase]);
        float4* dst = reinterpret_cast<float4*>(smem + SM_E2F2);
        dst[tid]       = src[tid];
        dst[tid + 256] = src[tid + 256];
    }

    // ---- preload h tile 0 (fp16x2 words) via cp.async
    {
        const uint32_t* src = &g_w16[(size_t)(jbase >> 1) * 64];
#pragma unroll
        for (int v = 0; v < 4; v++) {
            const int id = tid + v * 256;          // 0..1023 16B units
            const int jp = id >> 4, u = id & 15;
            cp_async16(sb + SM_H0 + jp * HROW + u * 16, src + jp * 64 + u * 4);
        }
        CP_COMMIT();
    }

    // ---- pack adj tile 0 masks (prologue; latency exposed once)
    const int4* adjv = reinterpret_cast<const int4*>(adj);
    {
        const int4* psrc = adjv + (size_t)rbase * 2048 + (jbase >> 2);
        const uint32_t mdst = sb + SM_MASK + (uint32_t)w * 512;
#pragma unroll 4
        for (int r = 0; r < 32; r++) {
            const int4 m = psrc[(size_t)r * 2048 + lane];
            const uint32_t b0 = __ballot_sync(0xFFFFFFFFu, m.x != 0);
            const uint32_t b1 = __ballot_sync(0xFFFFFFFFu, m.y != 0);
            const uint32_t b2 = __ballot_sync(0xFFFFFFFFu, m.z != 0);
            const uint32_t b3 = __ballot_sync(0xFFFFFFFFu, m.w != 0);
            if (lane == 0)
                asm volatile("st.shared.v4.b32 [%0], {%1,%2,%3,%4};"
                             :: "r"(mdst + r * 16), "r"(b0), "r"(b1), "r"(b2), "r"(b3)
                             : "memory");
        }
    }

    const float2 ef0 = g_e1f1[rbase + g];
    const float2 ef1 = g_e1f1[rbase + g + 8];
    const float2 ef2 = g_e1f1[rbase + g + 16];
    const float2 ef3 = g_e1f1[rbase + g + 24];
    const int o = ctg >> 1;

    float C0[8][4], C1[8][4], S0[4], S1[4];
#pragma unroll
    for (int n = 0; n < 8; n++)
#pragma unroll
        for (int q = 0; q < 4; q++) { C0[n][q] = 0.f; C1[n][q] = 0.f; }
#pragma unroll
    for (int q = 0; q < 4; q++) { S0[q] = 0.f; S1[q] = 0.f; }

    for (int t = 0; t < 8; t++) {
        CP_WAIT(0);          // h tile t resident
        __syncthreads();     // h + masks for t ready; prev buffers free

        const uint32_t hb = (t & 1) ? SM_H1 : SM_H0;

        // mask regs for tile t (pre-shift by o)
        uint32_t mA0, mB0, mA1, mB1, mA2, mB2, mA3, mB3;
        {
            const uint32_t mb = sb + SM_MASK + (uint32_t)(t & 1) * 4096
                              + (uint32_t)w * 512 + (uint32_t)(ctg & 1) * 8;
            uint2 q0 = lds64u(mb + g * 16);
            uint2 q1 = lds64u(mb + (g + 8) * 16);
            uint2 q2 = lds64u(mb + (g + 16) * 16);
            uint2 q3 = lds64u(mb + (g + 24) * 16);
            mA0 = q0.x >> o; mB0 = q0.y >> o;
            mA1 = q1.x >> o; mB1 = q1.y >> o;
            mA2 = q2.x >> o; mB2 = q2.y >> o;
            mA3 = q3.x >> o; mB3 = q3.y >> o;
        }

        // issue h prefetch for t+1
        if (t < 7) {
            const uint32_t hn = (t & 1) ? SM_H0 : SM_H1;
            const uint32_t* src = &g_w16[(size_t)((jbase >> 1) + (t + 1) * 64) * 64];
#pragma unroll
            for (int v = 0; v < 4; v++) {
                const int id = tid + v * 256;
                const int jp = id >> 4, u = id & 15;
                cp_async16(sb + hn + jp * HROW + u * 16, src + jp * 64 + u * 4);
            }
        }
        CP_COMMIT();

        // pack pipeline setup for tile t+1
        const int4* psrc = adjv + (size_t)rbase * 2048 + ((jbase + (t + 1) * 128) >> 2);
        const uint32_t mdst = sb + SM_MASK + (uint32_t)((t + 1) & 1) * 4096
                            + (uint32_t)w * 512;
        int4 pv0, pv1, pv2, pv3;
        if (t < 7) {
            pv0 = psrc[lane];
            pv1 = psrc[2048 + lane];
            pv2 = psrc[2 * 2048 + lane];
            pv3 = psrc[3 * 2048 + lane];
        }

#pragma unroll
        for (int kk = 0; kk < 8; kk++) {
            const int jc = t * 128 + kk * 16;

            // column factors: {e2[c],f2[c],e2[c+1],f2[c+1]} for c = jc+2ctg, jc+2ctg+8
            const float4 c4 = lds128f(sb + SM_E2F2 + (jc + 2 * ctg) * 8);
            const float4 c8 = lds128f(sb + SM_E2F2 + (jc + 2 * ctg + 8) * 8);

            // P = adj ? max(E1*E2, F1*F2) : 0
            const float vL0 = fmaxf(ef0.x * c4.x, ef0.y * c4.y);
            const float vM0 = fmaxf(ef0.x * c4.z, ef0.y * c4.w);
            const float vH0 = fmaxf(ef0.x * c8.x, ef0.y * c8.y);
            const float vN0 = fmaxf(ef0.x * c8.z, ef0.y * c8.w);
            const float vL1 = fmaxf(ef1.x * c4.x, ef1.y * c4.y);
            const float vM1 = fmaxf(ef1.x * c4.z, ef1.y * c4.w);
            const float vH1 = fmaxf(ef1.x * c8.x, ef1.y * c8.y);
            const float vN1 = fmaxf(ef1.x * c8.z, ef1.y * c8.w);
            const float vL2 = fmaxf(ef2.x * c4.x, ef2.y * c4.y);
            const float vM2 = fmaxf(ef2.x * c4.z, ef2.y * c4.w);
            const float vH2 = fmaxf(ef2.x * c8.x, ef2.y * c8.y);
            const float vN2 = fmaxf(ef2.x * c8.z, ef2.y * c8.w);
            const float vL3 = fmaxf(ef3.x * c4.x, ef3.y * c4.y);
            const float vM3 = fmaxf(ef3.x * c4.z, ef3.y * c4.w);
            const float vH3 = fmaxf(ef3.x * c8.x, ef3.y * c8.y);
            const float vN3 = fmaxf(ef3.x * c8.z, ef3.y * c8.w);

            const uint32_t a0 = pack16(msel(mB0, 31, vM0), msel(mA0, 31, vL0));
            const uint32_t a1 = pack16(msel(mB1, 31, vM1), msel(mA1, 31, vL1));
            const uint32_t a2 = pack16(msel(mB0, 29, vN0), msel(mA0, 29, vH0));
            const uint32_t a3 = pack16(msel(mB1, 29, vN1), msel(mA1, 29, vH1));
            const uint32_t a4 = pack16(msel(mB2, 31, vM2), msel(mA2, 31, vL2));
            const uint32_t a5 = pack16(msel(mB3, 31, vM3), msel(mA3, 31, vL3));
            const uint32_t a6 = pack16(msel(mB2, 29, vN2), msel(mA2, 29, vH2));
            const uint32_t a7 = pack16(msel(mB3, 29, vN3), msel(mA3, 29, vH3));
            mA0 >>= 4; mB0 >>= 4; mA1 >>= 4; mB1 >>= 4;
            mA2 >>= 4; mB2 >>= 4; mA3 >>= 4; mB3 >>= 4;

            // B fragments: rows 8kk+ctg, +4; words g*8..g*8+7 per row
            const uint32_t rb = sb + hb + (uint32_t)(8 * kk + ctg) * HROW + (uint32_t)g * 32;
            const uint4 bl0 = lds128(rb);
            const uint4 bl1 = lds128(rb + 16);
            const uint4 bh0 = lds128(rb + 4 * HROW);
            const uint4 bh1 = lds128(rb + 4 * HROW + 16);

            mma_f16(C0[0], a0, a1, a2, a3, bl0.x, bh0.x);
            mma_f16(C1[0], a4, a5, a6, a7, bl0.x, bh0.x);
            mma_f16(C0[1], a0, a1, a2, a3, bl0.y, bh0.y);
            mma_f16(C1[1], a4, a5, a6, a7, bl0.y, bh0.y);
            mma_f16(C0[2], a0, a1, a2, a3, bl0.z, bh0.z);
            mma_f16(C1[2], a4, a5, a6, a7, bl0.z, bh0.z);
            mma_f16(C0[3], a0, a1, a2, a3, bl0.w, bh0.w);
            mma_f16(C1[3], a4, a5, a6, a7, bl0.w, bh0.w);
            mma_f16(C0[4], a0, a1, a2, a3, bl1.x, bh1.x);
            mma_f16(C1[4], a4, a5, a6, a7, bl1.x, bh1.x);
            mma_f16(C0[5], a0, a1, a2, a3, bl1.y, bh1.y);
            mma_f16(C1[5], a4, a5, a6, a7, bl1.y, bh1.y);
            mma_f16(C0[6], a0, a1, a2, a3, bl1.z, bh1.z);
            mma_f16(C1[6], a4, a5, a6, a7, bl1.z, bh1.z);
            mma_f16(C0[7], a0, a1, a2, a3, bl1.w, bh1.w);
            mma_f16(C1[7], a4, a5, a6, a7, bl1.w, bh1.w);
            mma_f16(S0, a0, a1, a2, a3, ONE2, ONE2);
            mma_f16(S1, a4, a5, a6, a7, ONE2, ONE2);

            // pack pipeline: ballot+store group kk (loaded ~1 kstep ago), load next
            if (t < 7) {
                {
                    const uint32_t b0 = __ballot_sync(0xFFFFFFFFu, pv0.x != 0);
                    const uint32_t b1 = __ballot_sync(0xFFFFFFFFu, pv0.y != 0);
                    const uint32_t b2 = __ballot_sync(0xFFFFFFFFu, pv0.z != 0);
                    const uint32_t b3 = __ballot_sync(0xFFFFFFFFu, pv0.w != 0);
                    if (lane == 0)
                        asm volatile("st.shared.v4.b32 [%0], {%1,%2,%3,%4};"
                                     :: "r"(mdst + (4 * kk) * 16),
                                        "r"(b0), "r"(b1), "r"(b2), "r"(b3) : "memory");
                }
                {
                    const uint32_t b0 = __ballot_sync(0xFFFFFFFFu, pv1.x != 0);
                    const uint32_t b1 = __ballot_sync(0xFFFFFFFFu, pv1.y != 0);
                    const uint32_t b2 = __ballot_sync(0xFFFFFFFFu, pv1.z != 0);
                    const uint32_t b3 = __ballot_sync(0xFFFFFFFFu, pv1.w != 0);
                    if (lane == 0)
                        asm volatile("st.shared.v4.b32 [%0], {%1,%2,%3,%4};"
                                     :: "r"(mdst + (4 * kk + 1) * 16),
                                        "r"(b0), "r"(b1), "r"(b2), "r"(b3) : "memory");
                }
                {
                    const uint32_t b0 = __ballot_sync(0xFFFFFFFFu, pv2.x != 0);
                    const uint32_t b1 = __ballot_sync(0xFFFFFFFFu, pv2.y != 0);
                    const uint32_t b2 = __ballot_sync(0xFFFFFFFFu, pv2.z != 0);
                    const uint32_t b3 = __ballot_sync(0xFFFFFFFFu, pv2.w != 0);
                    if (lane == 0)
                        asm volatile("st.shared.v4.b32 [%0], {%1,%2,%3,%4};"
                                     :: "r"(mdst + (4 * kk + 2) * 16),
                                        "r"(b0), "r"(b1), "r"(b2), "r"(b3) : "memory");
                }
                {
                    const uint32_t b0 = __ballot_sync(0xFFFFFFFFu, pv3.x != 0);
                    const uint32_t b1 = __ballot_sync(0xFFFFFFFFu, pv3.y != 0);
                    const uint32_t b2 = __ballot_sync(0xFFFFFFFFu, pv3.z != 0);
                    const uint32_t b3 = __ballot_sync(0xFFFFFFFFu, pv3.w != 0);
                    if (lane == 0)
                        asm volatile("st.shared.v4.b32 [%0], {%1,%2,%3,%4};"
                                     :: "r"(mdst + (4 * kk + 3) * 16),
                                        "r"(b0), "r"(b1), "r"(b2), "r"(b3) : "memory");
                }
                if (kk < 7) {
                    const int rr = 4 * kk + 4;
                    pv0 = psrc[(size_t)rr * 2048 + lane];
                    pv1 = psrc[(size_t)(rr + 1) * 2048 + lane];
                    pv2 = psrc[(size_t)(rr + 2) * 2048 + lane];
                    pv3 = psrc[(size_t)(rr + 3) * 2048 + lane];
                }
            }
        }
    }

    // ---- l write (S values identical across the 4 threads of each group)
    if (ctg == 0) {
        float* lp = &g_lpart[(size_t)jq * 8192];
        lp[rbase + g]      = S0[0];
        lp[rbase + g + 8]  = S0[2];
        lp[rbase + g + 16] = S1[0];
        lp[rbase + g + 24] = S1[2];
    }

    // ---- write D partials (TRUE f order): mma #nt covers f = nt*8 + mma-n
    float* d0 = &g_part[((size_t)jq * 8192 + rbase + g) * 64];
    float* d1 = d0 + 8 * 64;
    float* d2 = d0 + 16 * 64;
    float* d3 = d0 + 24 * 64;
#pragma unroll
    for (int nt = 0; nt < 8; nt++) {
        const int col = nt * 8 + 2 * ctg;
        *reinterpret_cast<float2*>(&d0[col]) = make_float2(C0[nt][0], C0[nt][1]);
        *reinterpret_cast<float2*>(&d1[col]) = make_float2(C0[nt][2], C0[nt][3]);
        *reinterpret_cast<float2*>(&d2[col]) = make_float2(C1[nt][0], C1[nt][1]);
        *reinterpret_cast<float2*>(&d3[col]) = make_float2(C1[nt][2], C1[nt][3]);
    }
}

// ============================================================================
// K3: combine 8 partials, normalize, elu.
// ============================================================================
__device__ __forceinline__ float eluf(float x) { return x > 0.f ? x : expm1f(x); }

__global__ void __launch_bounds__(256)
gat_final(float* __restrict__ out)
{
    const int gi = blockIdx.x * 256 + threadIdx.x;  // 0..131071
    const int i  = gi >> 4;
    const int c0 = (gi & 15) * 4;
    float4 acc = *reinterpret_cast<const float4*>(&g_part[(size_t)i * 64 + c0]);
    float l = g_lpart[i];
#pragma unroll
    for (int q = 1; q < 8; q++) {
        const float4 d = *reinterpret_cast<const float4*>(
            &g_part[((size_t)q * 8192 + i) * 64 + c0]);
        acc.x += d.x; acc.y += d.y; acc.z += d.z; acc.w += d.w;
        l += g_lpart[(size_t)q * 8192 + i];
    }
    const float inv = 1.0f / l;
    float4 o;
    o.x = eluf(acc.x * inv);
    o.y = eluf(acc.y * inv);
    o.z = eluf(acc.z * inv);
    o.w = eluf(acc.w * inv);
    *reinterpret_cast<float4*>(&out[(size_t)i * 64 + c0]) = o;
}

// ============================================================================
extern "C" void kernel_launch(void* const* d_in, const int* in_sizes, int n_in,
                              void* d_out, int out_size)
{
    const float* inp = (const float*)d_in[0];
    const int*   adj = (const int*)d_in[1];
    const float* W   = (const float*)d_in[2];
    const float* a   = (const float*)d_in[3];
    float* out = (float*)d_out;

    cudaFuncSetAttribute((const void*)gat_prep,
                         cudaFuncAttributeMaxDynamicSharedMemorySize, PREP_SMEM);
    cudaFuncSetAttribute((const void*)gat_attn,
                         cudaFuncAttributeMaxDynamicSharedMemorySize, SMEM_TOTAL);

    gat_prep<<<512, 512, PREP_SMEM>>>(inp, W, a);
    gat_attn<<<256, 256, SMEM_TOTAL>>>(adj);
    gat_final<<<512, 256>>>(out);
}